// round 4
// baseline (speedup 1.0000x reference)
#include <cuda_runtime.h>

// Leapfrog (kick-drift-kick) integrator for a softened central potential.
//   accel(q) = -GM * q / (r*(r+A)^2 + 1e-12),  GM = A = 1
// Reference recomputes accel(q) at the top of each step on the q produced at
// the end of the previous step -> cache it: 65 accel evals instead of 128.
//
// Inputs (metadata order):
//   d_in[0] = ts       float32 [N]
//   d_in[1] = w0_lead  float32 [N,6]  (qx qy qz px py pz)
//   d_in[2] = w0_trail float32 [N,6]
//   d_in[3] = n_steps  int32   [1]
// Output: float32 [2N, 6], row 2i = trail_i, row 2i+1 = lead_i.

__device__ __forceinline__ float frsqrt_fast(float x) {
    float r;
    asm("rsqrt.approx.f32 %0, %1;" : "=f"(r) : "f"(x));
    return r;
}
__device__ __forceinline__ float frcp_fast(float x) {
    float r;
    asm("rcp.approx.f32 %0, %1;" : "=f"(r) : "f"(x));
    return r;
}

__device__ __forceinline__ void accel(float qx, float qy, float qz,
                                      float& ax, float& ay, float& az) {
    float r2 = fmaf(qx, qx, fmaf(qy, qy, qz * qz));
    float rinv = frsqrt_fast(r2);
    float r = r2 * rinv;                 // r = sqrt(r2)
    float t = r + 1.0f;                  // r + A_SCALE
    float denom = fmaf(r * t, t, 1e-12f);
    float c = -frcp_fast(denom);         // -GM / denom
    ax = c * qx;
    ay = c * qy;
    az = c * qz;
}

__global__ void __launch_bounds__(256)
leapfrog_kernel(const float* __restrict__ ts,
                const float* __restrict__ w_lead,
                const float* __restrict__ w_trail,
                const int* __restrict__ n_steps_p,
                float* __restrict__ out,
                int n) {
    int tid = blockIdx.x * blockDim.x + threadIdx.x;
    if (tid >= 2 * n) return;

    int i   = tid >> 1;
    int sel = tid & 1;  // 0 -> trail (even output row), 1 -> lead (odd row)

    const float* w0 = sel ? w_lead : w_trail;
    const int nst = *n_steps_p;

    float t_f = ts[n - 1] + 0.001f;
    float dt  = (t_f - ts[i]) / (float)nst;
    float h   = 0.5f * dt;

    // 6-float row, 24-byte stride -> 8-byte aligned: three float2 loads
    const float2* wp = reinterpret_cast<const float2*>(w0 + 6 * (size_t)i);
    float2 v0 = wp[0], v1 = wp[1], v2 = wp[2];
    float qx = v0.x, qy = v0.y, qz = v1.x;
    float px = v1.y, py = v2.x, pz = v2.y;

    float ax, ay, az;
    accel(qx, qy, qz, ax, ay, az);

#pragma unroll 4
    for (int s = 0; s < nst; s++) {
        // first half-kick (reuses cached accel of current q)
        px = fmaf(h, ax, px);
        py = fmaf(h, ay, py);
        pz = fmaf(h, az, pz);
        // drift
        qx = fmaf(dt, px, qx);
        qy = fmaf(dt, py, qy);
        qz = fmaf(dt, pz, qz);
        // new accel + second half-kick
        accel(qx, qy, qz, ax, ay, az);
        px = fmaf(h, ax, px);
        py = fmaf(h, ay, py);
        pz = fmaf(h, az, pz);
    }

    float2* op = reinterpret_cast<float2*>(out + 6 * (size_t)tid);
    op[0] = make_float2(qx, qy);
    op[1] = make_float2(qz, px);
    op[2] = make_float2(py, pz);
}

extern "C" void kernel_launch(void* const* d_in, const int* in_sizes, int n_in,
                              void* d_out, int out_size) {
    const float* ts      = (const float*)d_in[0];
    const float* w_lead  = (const float*)d_in[1];
    const float* w_trail = (const float*)d_in[2];
    const int*   n_steps = (const int*)d_in[3];
    float* out = (float*)d_out;

    int n = in_sizes[0];
    int total = 2 * n;
    int block = 256;
    int grid = (total + block - 1) / block;
    leapfrog_kernel<<<grid, block>>>(ts, w_lead, w_trail, n_steps, out, n);
}

// round 5
// speedup vs baseline: 1.5412x; 1.5412x over previous
#include <cuda_runtime.h>

// Leapfrog (kick-drift-kick) integrator, softened central potential:
//   accel(q) = -GM*q / (r*(r+A)^2 + 1e-12), GM = A = 1
//
// This version packs BOTH streams (lead, trail) of one particle into
// Blackwell f32x2 packed-math registers: one thread integrates two bodies
// with the same dt, one packed FMA per axis-op. Per-lane arithmetic is
// IEEE rn, bit-identical to the scalar version.
//
// Inputs: d_in[0]=ts f32[N], d_in[1]=w0_lead f32[N,6], d_in[2]=w0_trail f32[N,6],
//         d_in[3]=n_steps i32[1]
// Output: f32[2N,6], row 2i = trail_i, row 2i+1 = lead_i  (rows 2i,2i+1 are the
//         48 contiguous bytes this thread owns -> 3x float4 stores).

typedef unsigned long long u64;

__device__ __forceinline__ u64 pk(float lo, float hi) {
    u64 r; asm("mov.b64 %0, {%1,%2};" : "=l"(r) : "f"(lo), "f"(hi)); return r;
}
__device__ __forceinline__ void upk(u64 v, float& lo, float& hi) {
    asm("mov.b64 {%0,%1}, %2;" : "=f"(lo), "=f"(hi) : "l"(v));
}
__device__ __forceinline__ u64 fma2(u64 a, u64 b, u64 c) {
    u64 d; asm("fma.rn.f32x2 %0, %1, %2, %3;" : "=l"(d) : "l"(a), "l"(b), "l"(c)); return d;
}
__device__ __forceinline__ u64 mul2(u64 a, u64 b) {
    u64 d; asm("mul.rn.f32x2 %0, %1, %2;" : "=l"(d) : "l"(a), "l"(b)); return d;
}
__device__ __forceinline__ u64 add2(u64 a, u64 b) {
    u64 d; asm("add.rn.f32x2 %0, %1, %2;" : "=l"(d) : "l"(a), "l"(b)); return d;
}
__device__ __forceinline__ float frsqrt_fast(float x) {
    float r; asm("rsqrt.approx.f32 %0, %1;" : "=f"(r) : "f"(x)); return r;
}
__device__ __forceinline__ float frcp_fast(float x) {
    float r; asm("rcp.approx.f32 %0, %1;" : "=f"(r) : "f"(x)); return r;
}

// Packed accel for the (lead, trail) pair.
// Returns POSITIVE c = 1/(r(r+1)^2+eps) packed; kicks use negated half-step HN2.
__device__ __forceinline__ void accel2(u64 X, u64 Y, u64 Z, u64 ONE2, u64 EPS2,
                                       u64& AX, u64& AY, u64& AZ) {
    u64 S = mul2(X, X);
    S = fma2(Y, Y, S);
    S = fma2(Z, Z, S);               // r^2 pair
    float s0, s1; upk(S, s0, s1);
    u64 RI = pk(frsqrt_fast(s0), frsqrt_fast(s1));
    u64 R  = mul2(S, RI);            // r = r2 * rsqrt(r2)
    u64 T  = add2(R, ONE2);          // r + 1
    u64 U  = mul2(R, T);
    u64 D  = fma2(U, T, EPS2);       // r(r+1)^2 + 1e-12
    float d0, d1; upk(D, d0, d1);
    u64 C  = pk(frcp_fast(d0), frcp_fast(d1));
    AX = mul2(C, X);
    AY = mul2(C, Y);
    AZ = mul2(C, Z);
}

#define STEP()                                    \
    do {                                          \
        PX = fma2(HN2, AX, PX);                   \
        PY = fma2(HN2, AY, PY);                   \
        PZ = fma2(HN2, AZ, PZ);                   \
        X = fma2(DT2, PX, X);                     \
        Y = fma2(DT2, PY, Y);                     \
        Z = fma2(DT2, PZ, Z);                     \
        accel2(X, Y, Z, ONE2, EPS2, AX, AY, AZ);  \
        PX = fma2(HN2, AX, PX);                   \
        PY = fma2(HN2, AY, PY);                   \
        PZ = fma2(HN2, AZ, PZ);                   \
    } while (0)

__global__ void __launch_bounds__(64)
leapfrog2_kernel(const float* __restrict__ ts,
                 const float* __restrict__ w_lead,
                 const float* __restrict__ w_trail,
                 const int* __restrict__ n_steps_p,
                 float* __restrict__ out,
                 int n) {
    int i = blockIdx.x * blockDim.x + threadIdx.x;
    if (i >= n) return;

    const int nst = *n_steps_p;
    float t_f = ts[n - 1] + 0.001f;
    float dt  = (t_f - ts[i]) / (float)nst;
    float h   = 0.5f * dt;

    // Load both streams (24-byte rows, 8-byte aligned -> float2 x3 each)
    const float2* lp = reinterpret_cast<const float2*>(w_lead + 6 * (size_t)i);
    const float2* tp = reinterpret_cast<const float2*>(w_trail + 6 * (size_t)i);
    float2 l0 = lp[0], l1 = lp[1], l2 = lp[2];
    float2 t0 = tp[0], t1 = tp[1], t2 = tp[2];

    // Packed state: lo = lead, hi = trail
    u64 X  = pk(l0.x, t0.x), Y  = pk(l0.y, t0.y), Z  = pk(l1.x, t1.x);
    u64 PX = pk(l1.y, t1.y), PY = pk(l2.x, t2.x), PZ = pk(l2.y, t2.y);

    const u64 DT2  = pk(dt, dt);
    const u64 HN2  = pk(-h, -h);     // negated half step: kick = fma(HN2, c*q, p)
    const u64 ONE2 = pk(1.0f, 1.0f);
    const u64 EPS2 = pk(1e-12f, 1e-12f);

    u64 AX, AY, AZ;
    accel2(X, Y, Z, ONE2, EPS2, AX, AY, AZ);   // cached across steps

    if (nst == 64) {
#pragma unroll 16
        for (int s = 0; s < 64; s++) STEP();
    } else {
#pragma unroll 4
        for (int s = 0; s < nst; s++) STEP();
    }

    // Unpack and store: rows 2i (trail) and 2i+1 (lead) are 48 contiguous,
    // 16-aligned bytes -> 3x float4.
    float qxl, qxt, qyl, qyt, qzl, qzt, pxl, pxt, pyl, pyt, pzl, pzt;
    upk(X, qxl, qxt);  upk(Y, qyl, qyt);  upk(Z, qzl, qzt);
    upk(PX, pxl, pxt); upk(PY, pyl, pyt); upk(PZ, pzl, pzt);

    float4* op = reinterpret_cast<float4*>(out + 12 * (size_t)i);
    op[0] = make_float4(qxt, qyt, qzt, pxt);   // trail q, px
    op[1] = make_float4(pyt, pzt, qxl, qyl);   // trail py pz, lead qx qy
    op[2] = make_float4(qzl, pxl, pyl, pzl);   // lead qz, p
}

extern "C" void kernel_launch(void* const* d_in, const int* in_sizes, int n_in,
                              void* d_out, int out_size) {
    const float* ts      = (const float*)d_in[0];
    const float* w_lead  = (const float*)d_in[1];
    const float* w_trail = (const float*)d_in[2];
    const int*   n_steps = (const int*)d_in[3];
    float* out = (float*)d_out;

    int n = in_sizes[0];
    int block = 64;
    int grid = (n + block - 1) / block;   // 1024 blocks @ N=65536 -> 6.92/SM
    leapfrog2_kernel<<<grid, block>>>(ts, w_lead, w_trail, n_steps, out, n);
}